// round 2
// baseline (speedup 1.0000x reference)
#include <cuda_runtime.h>
#include <math.h>

// MixtureOfExpertFFN: x[B=4,S=2048,H=1024], Wg[H,8], W1[8,H,4096], b1[8,4096],
// W2[8,4096,H], b2[8,H]. top_k=2.
#define T_TOK 8192
#define H_DIM 1024
#define F_DIM 4096
#define E_NUM 8
#define NPAIR (2 * T_TOK)   // 16384 (token, expert) pairs

// -------- scratch (device globals; no allocation allowed) ----------------
__device__ float g_Hbuf[(size_t)NPAIR * F_DIM];  // 256 MiB intermediate h
__device__ int   g_tok[NPAIR];
__device__ float g_wt[NPAIR];
__device__ int   g_cnt[E_NUM];
__device__ int   g_off[E_NUM + 1];
__device__ int   g_cur[E_NUM];
__device__ int   g_tidx[NPAIR];
__device__ float g_tw[NPAIR];

// -------- init: zero output + per-expert counters ------------------------
__global__ void k_init(float* out, int n) {
    if (blockIdx.x == 0 && threadIdx.x < E_NUM) g_cnt[threadIdx.x] = 0;
    for (int i = blockIdx.x * blockDim.x + threadIdx.x; i < n;
         i += gridDim.x * blockDim.x)
        out[i] = 0.0f;
}

// -------- gating: logits -> top2 -> renormalized weights ------------------
// One warp per token. Softmax cancels under top-2 renormalization:
//   w1 = 1/(1+exp(l2-l1)), w2 = exp(l2-l1)*w1.
__global__ void k_gate(const float* __restrict__ x, const float* __restrict__ Wg) {
    __shared__ float sWg[H_DIM * E_NUM];  // 32 KB
    for (int i = threadIdx.x; i < (H_DIM * E_NUM) / 4; i += blockDim.x)
        ((float4*)sWg)[i] = ((const float4*)Wg)[i];
    __syncthreads();

    const int warp = threadIdx.x >> 5, lane = threadIdx.x & 31;
    const int t = blockIdx.x * 8 + warp;
    if (t >= T_TOK) return;
    const float* xr = x + (size_t)t * H_DIM;

    float acc[E_NUM];
#pragma unroll
    for (int e = 0; e < E_NUM; e++) acc[e] = 0.0f;
    for (int j = 0; j < H_DIM / 32; j++) {
        const int i = j * 32 + lane;
        const float xv = xr[i];
        const float* wrow = &sWg[i * E_NUM];
#pragma unroll
        for (int e = 0; e < E_NUM; e++) acc[e] += xv * wrow[e];
    }
#pragma unroll
    for (int off = 16; off > 0; off >>= 1)
#pragma unroll
        for (int e = 0; e < E_NUM; e++)
            acc[e] += __shfl_xor_sync(0xffffffffu, acc[e], off);

    if (lane == 0) {
        int i1 = 0; float l1 = acc[0];
#pragma unroll
        for (int e = 1; e < E_NUM; e++)
            if (acc[e] > l1) { l1 = acc[e]; i1 = e; }
        int i2 = -1; float l2 = -3.0e38f;
#pragma unroll
        for (int e = 0; e < E_NUM; e++)
            if (e != i1 && acc[e] > l2) { l2 = acc[e]; i2 = e; }
        const float r  = expf(l2 - l1);
        const float w1 = 1.0f / (1.0f + r);
        const float w2 = r * w1;
        g_tidx[2 * t] = i1; g_tidx[2 * t + 1] = i2;
        g_tw[2 * t]   = w1; g_tw[2 * t + 1]   = w2;
        atomicAdd(&g_cnt[i1], 1);
        atomicAdd(&g_cnt[i2], 1);
    }
}

// -------- exclusive prefix over 8 expert counts ---------------------------
__global__ void k_offsets() {
    if (threadIdx.x == 0) {
        int s = 0;
        for (int e = 0; e < E_NUM; e++) { g_off[e] = s; g_cur[e] = s; s += g_cnt[e]; }
        g_off[E_NUM] = s;
    }
}

// -------- scatter token ids into expert-contiguous pair slots -------------
__global__ void k_scatter() {
    const int t = blockIdx.x * blockDim.x + threadIdx.x;
    if (t >= T_TOK) return;
#pragma unroll
    for (int k = 0; k < 2; k++) {
        const int e = g_tidx[2 * t + k];
        const int p = atomicAdd(&g_cur[e], 1);
        g_tok[p] = t;
        g_wt[p]  = g_tw[2 * t + k];
    }
}

__device__ __forceinline__ float gelu_tanh(float v) {
    // JAX default gelu (approximate=True)
    const float c = 0.7978845608028654f * (v + 0.044715f * v * v * v);
    return 0.5f * v * (1.0f + tanhf(c));
}

// Micro-tile mapping (conflict-free LDS.128):
//   thread (ty = tid>>4, tx = tid&15) owns
//   rows {ty*4+0..3} U {64+ty*4+0..3}, cols {tx*4+0..3} U {64+tx*4+0..3}.
#define ROW_OF(i) ((ty << 2) + ((i) & 3) + (((i) >> 2) << 6))
#define COL_OF(j) ((tx << 2) + ((j) & 3) + (((j) >> 2) << 6))

// -------- GEMM1: h = gelu(X_gathered @ W1[e] + b1[e]) --------------------
// 128x128 tile, BK=16, 256 threads, 8x8 register micro-tile, double-buffered.
__global__ __launch_bounds__(256, 2)
void k_ffn1(const float* __restrict__ x, const float* __restrict__ W1,
            const float* __restrict__ b1) {
    const int e    = blockIdx.z;
    const int base = g_off[e];
    const int cnt  = g_off[e + 1] - base;
    const int m0   = blockIdx.x * 128;
    if (m0 >= cnt) return;
    const int n0 = blockIdx.y * 128;

    __shared__ float As[2][16][128];
    __shared__ float Bs[2][16][128];
    __shared__ int   sRow[128];

    const int tid = threadIdx.x;
    if (tid < 128) {
        const int r = m0 + tid;
        sRow[tid] = (r < cnt) ? g_tok[base + r] * H_DIM : -1;
    }
    __syncthreads();

    const float* W1e = W1 + (size_t)e * H_DIM * F_DIM;

    // per-thread load coordinates (fixed across K-tiles)
    const int aRow0 = (tid) >> 2,        aQ0 = (tid) & 3;
    const int aRow1 = (tid + 256) >> 2,  aQ1 = (tid + 256) & 3;
    const int bR0   = (tid) >> 5,        bC0 = ((tid) & 31) * 4;
    const int bR1   = (tid + 256) >> 5,  bC1 = ((tid + 256) & 31) * 4;
    const int aOff0 = sRow[aRow0], aOff1 = sRow[aRow1];

    float acc[8][8];
#pragma unroll
    for (int i = 0; i < 8; i++)
#pragma unroll
        for (int j = 0; j < 8; j++) acc[i][j] = 0.0f;

    const int ty = tid >> 4, tx = tid & 15;

    // ---- prologue: tile 0 straight to smem buffer 0 ----
    {
        float4 va0 = make_float4(0.f,0.f,0.f,0.f), va1 = va0;
        if (aOff0 >= 0) va0 = *(const float4*)&x[aOff0 + aQ0 * 4];
        if (aOff1 >= 0) va1 = *(const float4*)&x[aOff1 + aQ1 * 4];
        As[0][aQ0*4+0][aRow0]=va0.x; As[0][aQ0*4+1][aRow0]=va0.y;
        As[0][aQ0*4+2][aRow0]=va0.z; As[0][aQ0*4+3][aRow0]=va0.w;
        As[0][aQ1*4+0][aRow1]=va1.x; As[0][aQ1*4+1][aRow1]=va1.y;
        As[0][aQ1*4+2][aRow1]=va1.z; As[0][aQ1*4+3][aRow1]=va1.w;
        *(float4*)&Bs[0][bR0][bC0] = *(const float4*)&W1e[(size_t)bR0 * F_DIM + n0 + bC0];
        *(float4*)&Bs[0][bR1][bC1] = *(const float4*)&W1e[(size_t)bR1 * F_DIM + n0 + bC1];
    }
    __syncthreads();

    const int KT = H_DIM / 16;
    for (int kt = 0; kt < KT; kt++) {
        const int buf = kt & 1;
        float4 va0, va1, vb0, vb1;
        if (kt + 1 < KT) {
            const int k1 = (kt + 1) * 16;
            va0 = make_float4(0.f,0.f,0.f,0.f); va1 = va0;
            if (aOff0 >= 0) va0 = *(const float4*)&x[aOff0 + k1 + aQ0 * 4];
            if (aOff1 >= 0) va1 = *(const float4*)&x[aOff1 + k1 + aQ1 * 4];
            vb0 = *(const float4*)&W1e[(size_t)(k1 + bR0) * F_DIM + n0 + bC0];
            vb1 = *(const float4*)&W1e[(size_t)(k1 + bR1) * F_DIM + n0 + bC1];
        }
#pragma unroll
        for (int kk = 0; kk < 16; kk++) {
            float a[8], b[8];
#pragma unroll
            for (int i = 0; i < 4; i++) { a[i]   = As[buf][kk][ty*4 + i];
                                          a[4+i] = As[buf][kk][64 + ty*4 + i]; }
#pragma unroll
            for (int j = 0; j < 4; j++) { b[j]   = Bs[buf][kk][tx*4 + j];
                                          b[4+j] = Bs[buf][kk][64 + tx*4 + j]; }
#pragma unroll
            for (int i = 0; i < 8; i++)
#pragma unroll
                for (int j = 0; j < 8; j++) acc[i][j] += a[i] * b[j];
        }
        if (kt + 1 < KT) {
            const int nb = buf ^ 1;
            As[nb][aQ0*4+0][aRow0]=va0.x; As[nb][aQ0*4+1][aRow0]=va0.y;
            As[nb][aQ0*4+2][aRow0]=va0.z; As[nb][aQ0*4+3][aRow0]=va0.w;
            As[nb][aQ1*4+0][aRow1]=va1.x; As[nb][aQ1*4+1][aRow1]=va1.y;
            As[nb][aQ1*4+2][aRow1]=va1.z; As[nb][aQ1*4+3][aRow1]=va1.w;
            *(float4*)&Bs[nb][bR0][bC0] = vb0;
            *(float4*)&Bs[nb][bR1][bC1] = vb1;
            __syncthreads();
        }
    }

    // epilogue: +b1, gelu, store h
#pragma unroll
    for (int i = 0; i < 8; i++) {
        const int gr = m0 + ROW_OF(i);
        if (gr < cnt) {
            float* Hrow = &g_Hbuf[(size_t)(base + gr) * F_DIM];
#pragma unroll
            for (int j = 0; j < 8; j++) {
                const int n = n0 + COL_OF(j);
                const float v = acc[i][j] + b1[e * F_DIM + n];
                Hrow[n] = gelu_tanh(v);
            }
        }
    }
}

// -------- GEMM2: out[tok] += w * (h @ W2[e] + b2[e]) ---------------------
__global__ __launch_bounds__(256, 2)
void k_ffn2(const float* __restrict__ W2, const float* __restrict__ b2,
            float* __restrict__ out) {
    const int e    = blockIdx.z;
    const int base = g_off[e];
    const int cnt  = g_off[e + 1] - base;
    const int m0   = blockIdx.x * 128;
    if (m0 >= cnt) return;
    const int n0 = blockIdx.y * 128;

    __shared__ float As[2][16][128];
    __shared__ float Bs[2][16][128];

    const int tid = threadIdx.x;
    const float* W2e = W2 + (size_t)e * F_DIM * H_DIM;

    const int aRow0 = (tid) >> 2,        aQ0 = (tid) & 3;
    const int aRow1 = (tid + 256) >> 2,  aQ1 = (tid + 256) & 3;
    const int bR0   = (tid) >> 5,        bC0 = ((tid) & 31) * 4;
    const int bR1   = (tid + 256) >> 5,  bC1 = ((tid + 256) & 31) * 4;
    const bool aOk0 = (m0 + aRow0) < cnt;
    const bool aOk1 = (m0 + aRow1) < cnt;
    const float* Ar0 = &g_Hbuf[(size_t)(base + m0 + aRow0) * F_DIM];
    const float* Ar1 = &g_Hbuf[(size_t)(base + m0 + aRow1) * F_DIM];

    float acc[8][8];
#pragma unroll
    for (int i = 0; i < 8; i++)
#pragma unroll
        for (int j = 0; j < 8; j++) acc[i][j] = 0.0f;

    const int ty = tid >> 4, tx = tid & 15;

    {
        float4 va0 = make_float4(0.f,0.f,0.f,0.f), va1 = va0;
        if (aOk0) va0 = *(const float4*)&Ar0[aQ0 * 4];
        if (aOk1) va1 = *(const float4*)&Ar1[aQ1 * 4];
        As[0][aQ0*4+0][aRow0]=va0.x; As[0][aQ0*4+1][aRow0]=va0.y;
        As[0][aQ0*4+2][aRow0]=va0.z; As[0][aQ0*4+3][aRow0]=va0.w;
        As[0][aQ1*4+0][aRow1]=va1.x; As[0][aQ1*4+1][aRow1]=va1.y;
        As[0][aQ1*4+2][aRow1]=va1.z; As[0][aQ1*4+3][aRow1]=va1.w;
        *(float4*)&Bs[0][bR0][bC0] = *(const float4*)&W2e[(size_t)bR0 * H_DIM + n0 + bC0];
        *(float4*)&Bs[0][bR1][bC1] = *(const float4*)&W2e[(size_t)bR1 * H_DIM + n0 + bC1];
    }
    __syncthreads();

    const int KT = F_DIM / 16;
    for (int kt = 0; kt < KT; kt++) {
        const int buf = kt & 1;
        float4 va0, va1, vb0, vb1;
        if (kt + 1 < KT) {
            const int k1 = (kt + 1) * 16;
            va0 = make_float4(0.f,0.f,0.f,0.f); va1 = va0;
            if (aOk0) va0 = *(const float4*)&Ar0[k1 + aQ0 * 4];
            if (aOk1) va1 = *(const float4*)&Ar1[k1 + aQ1 * 4];
            vb0 = *(const float4*)&W2e[(size_t)(k1 + bR0) * H_DIM + n0 + bC0];
            vb1 = *(const float4*)&W2e[(size_t)(k1 + bR1) * H_DIM + n0 + bC1];
        }
#pragma unroll
        for (int kk = 0; kk < 16; kk++) {
            float a[8], b[8];
#pragma unroll
            for (int i = 0; i < 4; i++) { a[i]   = As[buf][kk][ty*4 + i];
                                          a[4+i] = As[buf][kk][64 + ty*4 + i]; }
#pragma unroll
            for (int j = 0; j < 4; j++) { b[j]   = Bs[buf][kk][tx*4 + j];
                                          b[4+j] = Bs[buf][kk][64 + tx*4 + j]; }
#pragma unroll
            for (int i = 0; i < 8; i++)
#pragma unroll
                for (int j = 0; j < 8; j++) acc[i][j] += a[i] * b[j];
        }
        if (kt + 1 < KT) {
            const int nb = buf ^ 1;
            As[nb][aQ0*4+0][aRow0]=va0.x; As[nb][aQ0*4+1][aRow0]=va0.y;
            As[nb][aQ0*4+2][aRow0]=va0.z; As[nb][aQ0*4+3][aRow0]=va0.w;
            As[nb][aQ1*4+0][aRow1]=va1.x; As[nb][aQ1*4+1][aRow1]=va1.y;
            As[nb][aQ1*4+2][aRow1]=va1.z; As[nb][aQ1*4+3][aRow1]=va1.w;
            *(float4*)&Bs[nb][bR0][bC0] = vb0;
            *(float4*)&Bs[nb][bR1][bC1] = vb1;
            __syncthreads();
        }
    }

    // epilogue: +b2, scale by combine weight, atomic accumulate into out.
    // Each out element receives exactly 2 atomic adds onto 0.0; float add is
    // commutative -> bitwise deterministic.
#pragma unroll
    for (int i = 0; i < 8; i++) {
        const int gr = m0 + ROW_OF(i);
        if (gr < cnt) {
            const int   tok = g_tok[base + gr];
            const float w   = g_wt[base + gr];
            float* orow = out + (size_t)tok * H_DIM;
#pragma unroll
            for (int j = 0; j < 8; j++) {
                const int n = n0 + COL_OF(j);
                atomicAdd(&orow[n], w * (acc[i][j] + b2[e * H_DIM + n]));
            }
        }
    }
}

extern "C" void kernel_launch(void* const* d_in, const int* in_sizes, int n_in,
                              void* d_out, int out_size) {
    const float* x  = (const float*)d_in[0];
    const float* Wg = (const float*)d_in[1];
    const float* W1 = (const float*)d_in[2];
    const float* b1 = (const float*)d_in[3];
    const float* W2 = (const float*)d_in[4];
    const float* b2 = (const float*)d_in[5];
    float* out = (float*)d_out;

    k_init<<<2048, 256>>>(out, out_size);
    k_gate<<<T_TOK / 8, 256>>>(x, Wg);
    k_offsets<<<1, 32>>>();
    k_scatter<<<T_TOK / 256, 256>>>();

    dim3 g1(64, F_DIM / 128, E_NUM);   // m-tiles (worst case 8192 rows), n-tiles, experts
    k_ffn1<<<g1, 256>>>(x, W1, b1);

    dim3 g2(64, H_DIM / 128, E_NUM);
    k_ffn2<<<g2, 256>>>(W2, b2, out);
}

// round 4
// speedup vs baseline: 2.4789x; 2.4789x over previous
#include <cuda_runtime.h>
#include <cuda_bf16.h>
#include <math.h>
#include <stdint.h>

// MixtureOfExpertFFN: x[B=4,S=2048,H=1024], Wg[H,8], W1[8,H,4096], b1[8,4096],
// W2[8,4096,H], b2[8,H]. top_k=2.
#define T_TOK 8192
#define H_DIM 1024
#define F_DIM 4096
#define E_NUM 8
#define NPAIR (2 * T_TOK)   // 16384 (token, expert) pairs

// -------- scratch (device globals; no allocation allowed) ----------------
__device__ float g_Hbuf[(size_t)NPAIR * F_DIM];  // 256 MiB intermediate h
__device__ int   g_tok[NPAIR];
__device__ float g_wt[NPAIR];
__device__ int   g_cnt[E_NUM];
__device__ int   g_off[E_NUM + 1];
__device__ int   g_cur[E_NUM];
__device__ int   g_tidx[NPAIR];
__device__ float g_tw[NPAIR];

// -------- init ------------------------------------------------------------
__global__ void k_init(float* out, int n) {
    if (blockIdx.x == 0 && threadIdx.x < E_NUM) g_cnt[threadIdx.x] = 0;
    for (int i = blockIdx.x * blockDim.x + threadIdx.x; i < n;
         i += gridDim.x * blockDim.x)
        out[i] = 0.0f;
}

// -------- gating ----------------------------------------------------------
__global__ void k_gate(const float* __restrict__ x, const float* __restrict__ Wg) {
    __shared__ float sWg[H_DIM * E_NUM];
    for (int i = threadIdx.x; i < (H_DIM * E_NUM) / 4; i += blockDim.x)
        ((float4*)sWg)[i] = ((const float4*)Wg)[i];
    __syncthreads();

    const int warp = threadIdx.x >> 5, lane = threadIdx.x & 31;
    const int t = blockIdx.x * 8 + warp;
    if (t >= T_TOK) return;
    const float* xr = x + (size_t)t * H_DIM;

    float acc[E_NUM];
#pragma unroll
    for (int e = 0; e < E_NUM; e++) acc[e] = 0.0f;
    for (int j = 0; j < H_DIM / 32; j++) {
        const int i = j * 32 + lane;
        const float xv = xr[i];
        const float* wrow = &sWg[i * E_NUM];
#pragma unroll
        for (int e = 0; e < E_NUM; e++) acc[e] += xv * wrow[e];
    }
#pragma unroll
    for (int off = 16; off > 0; off >>= 1)
#pragma unroll
        for (int e = 0; e < E_NUM; e++)
            acc[e] += __shfl_xor_sync(0xffffffffu, acc[e], off);

    if (lane == 0) {
        int i1 = 0; float l1 = acc[0];
#pragma unroll
        for (int e = 1; e < E_NUM; e++)
            if (acc[e] > l1) { l1 = acc[e]; i1 = e; }
        int i2 = -1; float l2 = -3.0e38f;
#pragma unroll
        for (int e = 0; e < E_NUM; e++)
            if (e != i1 && acc[e] > l2) { l2 = acc[e]; i2 = e; }
        const float r  = expf(l2 - l1);
        const float w1 = 1.0f / (1.0f + r);
        const float w2 = r * w1;
        g_tidx[2 * t] = i1; g_tidx[2 * t + 1] = i2;
        g_tw[2 * t]   = w1; g_tw[2 * t + 1]   = w2;
        atomicAdd(&g_cnt[i1], 1);
        atomicAdd(&g_cnt[i2], 1);
    }
}

__global__ void k_offsets() {
    if (threadIdx.x == 0) {
        int s = 0;
        for (int e = 0; e < E_NUM; e++) { g_off[e] = s; g_cur[e] = s; s += g_cnt[e]; }
        g_off[E_NUM] = s;
    }
}

__global__ void k_scatter() {
    const int t = blockIdx.x * blockDim.x + threadIdx.x;
    if (t >= T_TOK) return;
#pragma unroll
    for (int k = 0; k < 2; k++) {
        const int e = g_tidx[2 * t + k];
        const int p = atomicAdd(&g_cur[e], 1);
        g_tok[p] = t;
        g_wt[p]  = g_tw[2 * t + k];
    }
}

__device__ __forceinline__ float gelu_tanh(float v) {
    const float c = 0.7978845608028654f * (v + 0.044715f * v * v * v);
    return 0.5f * v * (1.0f + tanhf(c));
}

// ===================== tensor-core machinery ==============================
#define AS 24    // A smem row stride (16 + 8 pad) -> conflict-free ldmatrix
#define BS 136   // B smem row stride (128 + 8 pad) -> conflict-free ldmatrix

__device__ __forceinline__ uint32_t s2u(const void* p) {
    return (uint32_t)__cvta_generic_to_shared(p);
}
__device__ __forceinline__ uint32_t pk(__nv_bfloat16 a, __nv_bfloat16 b) {
    __nv_bfloat162 t; t.x = a; t.y = b;
    return *reinterpret_cast<uint32_t*>(&t);
}
// split float4 into hi/lo bf16 pairs (packed 2-per-u32, ascending k)
__device__ __forceinline__ void split4(float4 v, uint2& hi, uint2& lo) {
    __nv_bfloat16 h0 = __float2bfloat16(v.x), h1 = __float2bfloat16(v.y);
    __nv_bfloat16 h2 = __float2bfloat16(v.z), h3 = __float2bfloat16(v.w);
    __nv_bfloat16 l0 = __float2bfloat16(v.x - __bfloat162float(h0));
    __nv_bfloat16 l1 = __float2bfloat16(v.y - __bfloat162float(h1));
    __nv_bfloat16 l2 = __float2bfloat16(v.z - __bfloat162float(h2));
    __nv_bfloat16 l3 = __float2bfloat16(v.w - __bfloat162float(h3));
    hi.x = pk(h0, h1); hi.y = pk(h2, h3);
    lo.x = pk(l0, l1); lo.y = pk(l2, l3);
}
__device__ __forceinline__ void ldsm_x4(uint32_t a, uint32_t* r) {
    asm volatile("ldmatrix.sync.aligned.m8n8.x4.shared.b16 {%0,%1,%2,%3}, [%4];\n"
        : "=r"(r[0]), "=r"(r[1]), "=r"(r[2]), "=r"(r[3]) : "r"(a));
}
__device__ __forceinline__ void ldsm_x4t(uint32_t a, uint32_t* r) {
    asm volatile("ldmatrix.sync.aligned.m8n8.x4.trans.shared.b16 {%0,%1,%2,%3}, [%4];\n"
        : "=r"(r[0]), "=r"(r[1]), "=r"(r[2]), "=r"(r[3]) : "r"(a));
}
__device__ __forceinline__ void mma16816(float* c, const uint32_t* a,
                                         uint32_t b0, uint32_t b1) {
    asm volatile(
        "mma.sync.aligned.m16n8k16.row.col.f32.bf16.bf16.f32 "
        "{%0,%1,%2,%3}, {%4,%5,%6,%7}, {%8,%9}, {%0,%1,%2,%3};\n"
        : "+f"(c[0]), "+f"(c[1]), "+f"(c[2]), "+f"(c[3])
        : "r"(a[0]), "r"(a[1]), "r"(a[2]), "r"(a[3]), "r"(b0), "r"(b1));
}

// -------- GEMM1: h = gelu(X_gathered @ W1[e] + b1[e]) ---------------------
// 128x128 CTA tile, BK=16, 256 thr (8 warps, 2x4 grid of 64x32 warp tiles),
// bf16 3-term split-precision mma, double-buffered single-sync pipeline.
__global__ __launch_bounds__(256)
void k_ffn1(const float* __restrict__ x, const float* __restrict__ W1,
            const float* __restrict__ b1) {
    const int e    = blockIdx.z;
    const int base = g_off[e];
    const int cnt  = g_off[e + 1] - base;
    const int m0   = blockIdx.x * 128;
    if (m0 >= cnt) return;
    const int n0 = blockIdx.y * 128;

    __shared__ __align__(16) __nv_bfloat16 Ah[2][128][AS];
    __shared__ __align__(16) __nv_bfloat16 Al[2][128][AS];
    __shared__ __align__(16) __nv_bfloat16 Bh[2][16][BS];
    __shared__ __align__(16) __nv_bfloat16 Bl[2][16][BS];
    __shared__ int sRow[128];

    const int tid = threadIdx.x;
    if (tid < 128) {
        const int r = m0 + tid;
        sRow[tid] = (r < cnt) ? g_tok[base + r] * H_DIM : -1;
    }
    __syncthreads();

    const float* W1e = W1 + (size_t)e * H_DIM * F_DIM;

    const int aRow0 = tid >> 2,         aQ0 = tid & 3;
    const int aRow1 = (tid + 256) >> 2, aQ1 = (tid + 256) & 3;
    const int bR0   = tid >> 5,         bC0 = (tid & 31) * 4;
    const int bR1   = (tid + 256) >> 5, bC1 = ((tid + 256) & 31) * 4;
    const int aOff0 = sRow[aRow0], aOff1 = sRow[aRow1];

    const int w = tid >> 5, lane = tid & 31;
    const int wm = (w & 1) * 64, wn = (w >> 1) * 32;

    // per-lane ldmatrix source coords
    const int aLRow = wm + (lane & 15);         // + mt*16
    const int aLK   = (lane >> 4) * 8;
    const int bLK   = lane & 15;
    const int bLN   = wn + ((lane >> 4) * 8);   // + 0 / +16 for n-tile pairs

    float acc[4][4][4];
#pragma unroll
    for (int i = 0; i < 4; i++)
#pragma unroll
        for (int j = 0; j < 4; j++)
#pragma unroll
            for (int r = 0; r < 4; r++) acc[i][j][r] = 0.0f;

    auto ldA = [&](int kb, float4& va0, float4& va1) {
        va0 = make_float4(0.f, 0.f, 0.f, 0.f); va1 = va0;
        if (aOff0 >= 0) va0 = *(const float4*)&x[aOff0 + kb + aQ0 * 4];
        if (aOff1 >= 0) va1 = *(const float4*)&x[aOff1 + kb + aQ1 * 4];
    };
    auto ldB = [&](int kb, float4& vb0, float4& vb1) {
        vb0 = *(const float4*)&W1e[(size_t)(kb + bR0) * F_DIM + n0 + bC0];
        vb1 = *(const float4*)&W1e[(size_t)(kb + bR1) * F_DIM + n0 + bC1];
    };
    auto store = [&](int nb, float4 va0, float4 va1, float4 vb0, float4 vb1) {
        uint2 hi, lo;
        split4(va0, hi, lo);
        *(uint2*)&Ah[nb][aRow0][aQ0 * 4] = hi; *(uint2*)&Al[nb][aRow0][aQ0 * 4] = lo;
        split4(va1, hi, lo);
        *(uint2*)&Ah[nb][aRow1][aQ1 * 4] = hi; *(uint2*)&Al[nb][aRow1][aQ1 * 4] = lo;
        split4(vb0, hi, lo);
        *(uint2*)&Bh[nb][bR0][bC0] = hi; *(uint2*)&Bl[nb][bR0][bC0] = lo;
        split4(vb1, hi, lo);
        *(uint2*)&Bh[nb][bR1][bC1] = hi; *(uint2*)&Bl[nb][bR1][bC1] = lo;
    };

    {   // prologue: tile 0
        float4 va0, va1, vb0, vb1;
        ldA(0, va0, va1); ldB(0, vb0, vb1);
        store(0, va0, va1, vb0, vb1);
    }
    __syncthreads();

    const int KT = H_DIM / 16;
    for (int kt = 0; kt < KT; kt++) {
        const int buf = kt & 1;
        float4 va0, va1, vb0, vb1;
        if (kt + 1 < KT) { ldA((kt + 1) * 16, va0, va1); ldB((kt + 1) * 16, vb0, vb1); }

        uint32_t ah[4][4], al[4][4], bh[4][2], bl[4][2], t4[4];
#pragma unroll
        for (int mt = 0; mt < 4; mt++) {
            ldsm_x4(s2u(&Ah[buf][aLRow + mt * 16][aLK]), ah[mt]);
            ldsm_x4(s2u(&Al[buf][aLRow + mt * 16][aLK]), al[mt]);
        }
        ldsm_x4t(s2u(&Bh[buf][bLK][bLN]), t4);
        bh[0][0] = t4[0]; bh[0][1] = t4[1]; bh[1][0] = t4[2]; bh[1][1] = t4[3];
        ldsm_x4t(s2u(&Bh[buf][bLK][bLN + 16]), t4);
        bh[2][0] = t4[0]; bh[2][1] = t4[1]; bh[3][0] = t4[2]; bh[3][1] = t4[3];
        ldsm_x4t(s2u(&Bl[buf][bLK][bLN]), t4);
        bl[0][0] = t4[0]; bl[0][1] = t4[1]; bl[1][0] = t4[2]; bl[1][1] = t4[3];
        ldsm_x4t(s2u(&Bl[buf][bLK][bLN + 16]), t4);
        bl[2][0] = t4[0]; bl[2][1] = t4[1]; bl[3][0] = t4[2]; bl[3][1] = t4[3];

#pragma unroll
        for (int mt = 0; mt < 4; mt++)
#pragma unroll
            for (int nt = 0; nt < 4; nt++) {
                mma16816(acc[mt][nt], ah[mt], bh[nt][0], bh[nt][1]);
                mma16816(acc[mt][nt], ah[mt], bl[nt][0], bl[nt][1]);
                mma16816(acc[mt][nt], al[mt], bh[nt][0], bh[nt][1]);
            }

        if (kt + 1 < KT) {
            store(buf ^ 1, va0, va1, vb0, vb1);
            __syncthreads();
        }
    }

    // epilogue: +b1, gelu, store h (pair-slot rows are contiguous)
#pragma unroll
    for (int mt = 0; mt < 4; mt++) {
        const int gr0 = m0 + wm + mt * 16 + (lane >> 2);
        const int gr1 = gr0 + 8;
#pragma unroll
        for (int nt = 0; nt < 4; nt++) {
            const int col = n0 + wn + nt * 8 + (lane & 3) * 2;
            const float2 bv = *(const float2*)&b1[e * F_DIM + col];
            if (gr0 < cnt) {
                float2 o = { gelu_tanh(acc[mt][nt][0] + bv.x),
                             gelu_tanh(acc[mt][nt][1] + bv.y) };
                *(float2*)&g_Hbuf[(size_t)(base + gr0) * F_DIM + col] = o;
            }
            if (gr1 < cnt) {
                float2 o = { gelu_tanh(acc[mt][nt][2] + bv.x),
                             gelu_tanh(acc[mt][nt][3] + bv.y) };
                *(float2*)&g_Hbuf[(size_t)(base + gr1) * F_DIM + col] = o;
            }
        }
    }
}

// -------- GEMM2: out[tok] += w * (h @ W2[e] + b2[e]) ----------------------
__global__ __launch_bounds__(256)
void k_ffn2(const float* __restrict__ W2, const float* __restrict__ b2,
            float* __restrict__ out) {
    const int e    = blockIdx.z;
    const int base = g_off[e];
    const int cnt  = g_off[e + 1] - base;
    const int m0   = blockIdx.x * 128;
    if (m0 >= cnt) return;
    const int n0 = blockIdx.y * 128;

    __shared__ __align__(16) __nv_bfloat16 Ah[2][128][AS];
    __shared__ __align__(16) __nv_bfloat16 Al[2][128][AS];
    __shared__ __align__(16) __nv_bfloat16 Bh[2][16][BS];
    __shared__ __align__(16) __nv_bfloat16 Bl[2][16][BS];

    const int tid = threadIdx.x;
    const float* W2e = W2 + (size_t)e * F_DIM * H_DIM;

    const int aRow0 = tid >> 2,         aQ0 = tid & 3;
    const int aRow1 = (tid + 256) >> 2, aQ1 = (tid + 256) & 3;
    const int bR0   = tid >> 5,         bC0 = (tid & 31) * 4;
    const int bR1   = (tid + 256) >> 5, bC1 = ((tid + 256) & 31) * 4;
    const bool aOk0 = (m0 + aRow0) < cnt;
    const bool aOk1 = (m0 + aRow1) < cnt;
    const float* Ar0 = &g_Hbuf[(size_t)(base + m0 + aRow0) * F_DIM];
    const float* Ar1 = &g_Hbuf[(size_t)(base + m0 + aRow1) * F_DIM];

    const int w = tid >> 5, lane = tid & 31;
    const int wm = (w & 1) * 64, wn = (w >> 1) * 32;
    const int aLRow = wm + (lane & 15);
    const int aLK   = (lane >> 4) * 8;
    const int bLK   = lane & 15;
    const int bLN   = wn + ((lane >> 4) * 8);

    float acc[4][4][4];
#pragma unroll
    for (int i = 0; i < 4; i++)
#pragma unroll
        for (int j = 0; j < 4; j++)
#pragma unroll
            for (int r = 0; r < 4; r++) acc[i][j][r] = 0.0f;

    auto ldA = [&](int kb, float4& va0, float4& va1) {
        va0 = make_float4(0.f, 0.f, 0.f, 0.f); va1 = va0;
        if (aOk0) va0 = *(const float4*)&Ar0[kb + aQ0 * 4];
        if (aOk1) va1 = *(const float4*)&Ar1[kb + aQ1 * 4];
    };
    auto ldB = [&](int kb, float4& vb0, float4& vb1) {
        vb0 = *(const float4*)&W2e[(size_t)(kb + bR0) * H_DIM + n0 + bC0];
        vb1 = *(const float4*)&W2e[(size_t)(kb + bR1) * H_DIM + n0 + bC1];
    };
    auto store = [&](int nb, float4 va0, float4 va1, float4 vb0, float4 vb1) {
        uint2 hi, lo;
        split4(va0, hi, lo);
        *(uint2*)&Ah[nb][aRow0][aQ0 * 4] = hi; *(uint2*)&Al[nb][aRow0][aQ0 * 4] = lo;
        split4(va1, hi, lo);
        *(uint2*)&Ah[nb][aRow1][aQ1 * 4] = hi; *(uint2*)&Al[nb][aRow1][aQ1 * 4] = lo;
        split4(vb0, hi, lo);
        *(uint2*)&Bh[nb][bR0][bC0] = hi; *(uint2*)&Bl[nb][bR0][bC0] = lo;
        split4(vb1, hi, lo);
        *(uint2*)&Bh[nb][bR1][bC1] = hi; *(uint2*)&Bl[nb][bR1][bC1] = lo;
    };

    {
        float4 va0, va1, vb0, vb1;
        ldA(0, va0, va1); ldB(0, vb0, vb1);
        store(0, va0, va1, vb0, vb1);
    }
    __syncthreads();

    const int KT = F_DIM / 16;
    for (int kt = 0; kt < KT; kt++) {
        const int buf = kt & 1;
        float4 va0, va1, vb0, vb1;
        if (kt + 1 < KT) { ldA((kt + 1) * 16, va0, va1); ldB((kt + 1) * 16, vb0, vb1); }

        uint32_t ah[4][4], al[4][4], bh[4][2], bl[4][2], t4[4];
#pragma unroll
        for (int mt = 0; mt < 4; mt++) {
            ldsm_x4(s2u(&Ah[buf][aLRow + mt * 16][aLK]), ah[mt]);
            ldsm_x4(s2u(&Al[buf][aLRow + mt * 16][aLK]), al[mt]);
        }
        ldsm_x4t(s2u(&Bh[buf][bLK][bLN]), t4);
        bh[0][0] = t4[0]; bh[0][1] = t4[1]; bh[1][0] = t4[2]; bh[1][1] = t4[3];
        ldsm_x4t(s2u(&Bh[buf][bLK][bLN + 16]), t4);
        bh[2][0] = t4[0]; bh[2][1] = t4[1]; bh[3][0] = t4[2]; bh[3][1] = t4[3];
        ldsm_x4t(s2u(&Bl[buf][bLK][bLN]), t4);
        bl[0][0] = t4[0]; bl[0][1] = t4[1]; bl[1][0] = t4[2]; bl[1][1] = t4[3];
        ldsm_x4t(s2u(&Bl[buf][bLK][bLN + 16]), t4);
        bl[2][0] = t4[0]; bl[2][1] = t4[1]; bl[3][0] = t4[2]; bl[3][1] = t4[3];

#pragma unroll
        for (int mt = 0; mt < 4; mt++)
#pragma unroll
            for (int nt = 0; nt < 4; nt++) {
                mma16816(acc[mt][nt], ah[mt], bh[nt][0], bh[nt][1]);
                mma16816(acc[mt][nt], ah[mt], bl[nt][0], bl[nt][1]);
                mma16816(acc[mt][nt], al[mt], bh[nt][0], bh[nt][1]);
            }

        if (kt + 1 < KT) {
            store(buf ^ 1, va0, va1, vb0, vb1);
            __syncthreads();
        }
    }

    // epilogue: +b2, weight, atomic accumulate (exactly 2 commutative float
    // adds per output element onto 0.0 -> deterministic).
#pragma unroll
    for (int mt = 0; mt < 4; mt++) {
        const int gr0 = m0 + wm + mt * 16 + (lane >> 2);
        const int gr1 = gr0 + 8;
#pragma unroll
        for (int nt = 0; nt < 4; nt++) {
            const int col = n0 + wn + nt * 8 + (lane & 3) * 2;
            const float2 bv = *(const float2*)&b2[e * H_DIM + col];
            if (gr0 < cnt) {
                const int   tok = g_tok[base + gr0];
                const float wt  = g_wt[base + gr0];
                float* p = out + (size_t)tok * H_DIM + col;
                atomicAdd(p,     wt * (acc[mt][nt][0] + bv.x));
                atomicAdd(p + 1, wt * (acc[mt][nt][1] + bv.y));
            }
            if (gr1 < cnt) {
                const int   tok = g_tok[base + gr1];
                const float wt  = g_wt[base + gr1];
                float* p = out + (size_t)tok * H_DIM + col;
                atomicAdd(p,     wt * (acc[mt][nt][2] + bv.x));
                atomicAdd(p + 1, wt * (acc[mt][nt][3] + bv.y));
            }
        }
    }
}

extern "C" void kernel_launch(void* const* d_in, const int* in_sizes, int n_in,
                              void* d_out, int out_size) {
    const float* x  = (const float*)d_in[0];
    const float* Wg = (const float*)d_in[1];
    const float* W1 = (const float*)d_in[2];
    const float* b1 = (const float*)d_in[3];
    const float* W2 = (const float*)d_in[4];
    const float* b2 = (const float*)d_in[5];
    float* out = (float*)d_out;

    k_init<<<2048, 256>>>(out, out_size);
    k_gate<<<T_TOK / 8, 256>>>(x, Wg);
    k_offsets<<<1, 32>>>();
    k_scatter<<<T_TOK / 256, 256>>>();

    dim3 g1(64, F_DIM / 128, E_NUM);
    k_ffn1<<<g1, 256>>>(x, W1, b1);

    dim3 g2(64, H_DIM / 128, E_NUM);
    k_ffn2<<<g2, 256>>>(W2, b2, out);
}